// round 1
// baseline (speedup 1.0000x reference)
#include <cuda_runtime.h>
#include <cstdint>
#include <cstddef>

// Problem constants (fixed shapes for this bench)
#define RON_DT 0.042f
static constexpr int Bx = 128;   // batch
static constexpr int Tx = 1024;  // timesteps
static constexpr int Ix = 64;    // input dim
static constexpr int Hx = 512;   // hidden dim
static constexpr int NTHREADS = 512;

// Cluster partitioning: 16 clusters x 8 CTAs. Each cluster owns 8 batches,
// each CTA owns 64 j-columns of h2h (resident in SMEM for the whole run).
static constexpr int CLUSTER_SZ = 8;
static constexpr int JPC = 64;   // j columns per CTA
static constexpr int BPC = 8;    // batches per cluster

// SMEM layout (float offsets)
static constexpr int OFF_H2H = 0;                 // [512][64]  h2h column slice
static constexpr int OFF_X2H = 32768;             // [64][64]   x2h column slice
static constexpr int OFF_HY0 = 36864;             // [512][8]   hy mirror, phase 0 (k-major, b fastest)
static constexpr int OFF_HY1 = 40960;             // [512][8]   hy mirror, phase 1
static constexpr int OFF_XS0 = 45056;             // [64][8]    x staging, phase 0
static constexpr int OFF_XS1 = 45568;             // [64][8]    x staging, phase 1
static constexpr int OFF_RED = 46080;             // [16][512]  cross-warp reduction
static constexpr int SMEM_FLOATS = OFF_RED + 16 * 512;   // 54272 floats
static constexpr size_t SMEM_BYTES = (size_t)SMEM_FLOATS * 4;  // 217088 B

__device__ __forceinline__ uint32_t smem_u32(const void* p) {
    return (uint32_t)__cvta_generic_to_shared(p);
}

__device__ __forceinline__ void cluster_barrier() {
    asm volatile("barrier.cluster.arrive.aligned;" ::: "memory");
    asm volatile("barrier.cluster.wait.aligned;" ::: "memory");
}

// 16 FMAs: 2 j-columns (w2) x 8 batches (ha: b0..3, hb: b4..7)
__device__ __forceinline__ void acc16(float (&acc)[8][2], float2 w2, float4 ha, float4 hb) {
    acc[0][0] = fmaf(ha.x, w2.x, acc[0][0]); acc[0][1] = fmaf(ha.x, w2.y, acc[0][1]);
    acc[1][0] = fmaf(ha.y, w2.x, acc[1][0]); acc[1][1] = fmaf(ha.y, w2.y, acc[1][1]);
    acc[2][0] = fmaf(ha.z, w2.x, acc[2][0]); acc[2][1] = fmaf(ha.z, w2.y, acc[2][1]);
    acc[3][0] = fmaf(ha.w, w2.x, acc[3][0]); acc[3][1] = fmaf(ha.w, w2.y, acc[3][1]);
    acc[4][0] = fmaf(hb.x, w2.x, acc[4][0]); acc[4][1] = fmaf(hb.x, w2.y, acc[4][1]);
    acc[5][0] = fmaf(hb.y, w2.x, acc[5][0]); acc[5][1] = fmaf(hb.y, w2.y, acc[5][1]);
    acc[6][0] = fmaf(hb.z, w2.x, acc[6][0]); acc[6][1] = fmaf(hb.z, w2.y, acc[6][1]);
    acc[7][0] = fmaf(hb.w, w2.x, acc[7][0]); acc[7][1] = fmaf(hb.w, w2.y, acc[7][1]);
}

extern __shared__ float smem[];

__global__ void __cluster_dims__(CLUSTER_SZ, 1, 1) __launch_bounds__(NTHREADS, 1)
ron_cluster_kernel(const float* __restrict__ x,
                   const float* __restrict__ x2h,
                   const float* __restrict__ h2h,
                   const float* __restrict__ bias,
                   const float* __restrict__ gamma,
                   const float* __restrict__ eps,
                   float* __restrict__ out_states,
                   float* __restrict__ out_hy,
                   int write_hy)
{
    const int tid  = threadIdx.x;
    const int w    = tid >> 5;     // warp 0..15 -> k-slice
    const int lane = tid & 31;

    uint32_t rank_u;
    asm("mov.u32 %0, %%cluster_ctarank;" : "=r"(rank_u));
    const int r     = (int)rank_u;            // j-slice owner within cluster
    const int cl    = blockIdx.x >> 3;        // cluster id (contiguous blocks form a cluster)
    const int b0    = cl * BPC;               // first global batch of this cluster
    const int jbase = r * JPC;                // first global j of this CTA

    // ---- Prologue: load weight slices into SMEM (once for all 1024 steps) ----
    // h2h slice: [512][64] columns [jbase, jbase+64)
    #pragma unroll 4
    for (int it = 0; it < (Hx * JPC) / NTHREADS; ++it) {
        int idx = it * NTHREADS + tid;
        int k = idx >> 6, jj = idx & 63;
        smem[OFF_H2H + idx] = h2h[(size_t)k * Hx + jbase + jj];
    }
    // x2h slice: [64][64]
    #pragma unroll
    for (int it = 0; it < (Ix * JPC) / NTHREADS; ++it) {
        int idx = it * NTHREADS + tid;
        int i = idx >> 6, jj = idx & 63;
        smem[OFF_X2H + idx] = x2h[(size_t)i * Hx + jbase + jj];
    }
    // zero hy mirror phase 0 (initial hidden state)
    #pragma unroll
    for (int it = 0; it < (Hx * BPC) / NTHREADS; ++it)
        smem[OFF_HY0 + it * NTHREADS + tid] = 0.0f;

    // stage x for t=0 into xs phase 0: layout xs[i][b]
    {
        int bb = tid >> 6, i = tid & 63;
        smem[OFF_XS0 + i * 8 + bb] = x[(size_t)(b0 + bb) * Tx * Ix + i];
    }

    // Owner mapping for the update phase: thread tid owns (batch ob, column ojj)
    const int ob  = tid >> 6;
    const int ojj = tid & 63;
    const float g  = gamma[jbase + ojj];
    const float e  = eps[jbase + ojj];
    const float bi = bias[jbase + ojj];
    float hy = 0.0f, hz = 0.0f;

    // Precompute remote DSMEM base addresses of both hy mirrors in all 8 CTAs
    uint32_t remA[CLUSTER_SZ], remB[CLUSTER_SZ];
    {
        uint32_t locA = smem_u32(&smem[OFF_HY0]);
        uint32_t locB = smem_u32(&smem[OFF_HY1]);
        #pragma unroll
        for (int q = 0; q < CLUSTER_SZ; ++q) {
            asm("mapa.shared::cluster.u32 %0, %1, %2;" : "=r"(remA[q]) : "r"(locA), "r"(q));
            asm("mapa.shared::cluster.u32 %0, %1, %2;" : "=r"(remB[q]) : "r"(locB), "r"(q));
        }
    }

    cluster_barrier();  // prologue done everywhere before first step

    const int k0 = w * 32;   // this warp's k slice (recurrent matvec)
    const int i0 = w * 4;    // this warp's i slice (input projection)
    const int jj0 = lane * 2;

    for (int t = 0; t < Tx; ++t) {
        const int ph = t & 1;
        const float* hyp = smem + (ph ? OFF_HY1 : OFF_HY0);
        const float* xr  = smem + (ph ? OFF_XS1 : OFF_XS0);
        float*       xw  = smem + (ph ? OFF_XS0 : OFF_XS1);

        // Prefetch next timestep's x slice into the other staging buffer
        if (t + 1 < Tx) {
            int bb = tid >> 6, i = tid & 63;
            xw[i * 8 + bb] = x[(size_t)(b0 + bb) * Tx * Ix + (size_t)(t + 1) * Ix + i];
        }

        // ---- Partial matvec: this warp's k-slice, 2 j's x 8 batches per lane ----
        float acc[8][2];
        #pragma unroll
        for (int b = 0; b < 8; ++b) { acc[b][0] = 0.0f; acc[b][1] = 0.0f; }

        #pragma unroll 4
        for (int kk = 0; kk < 32; ++kk) {
            int k = k0 + kk;
            float2 w2 = *(const float2*)(smem + OFF_H2H + k * JPC + jj0);
            float4 ha = *(const float4*)(hyp + k * 8);
            float4 hb = *(const float4*)(hyp + k * 8 + 4);
            acc16(acc, w2, ha, hb);
        }
        // Input projection slice (i-range of this warp)
        #pragma unroll
        for (int ii = 0; ii < 4; ++ii) {
            int i = i0 + ii;
            float2 w2 = *(const float2*)(smem + OFF_X2H + i * JPC + jj0);
            float4 xa = *(const float4*)(xr + i * 8);
            float4 xb = *(const float4*)(xr + i * 8 + 4);
            acc16(acc, w2, xa, xb);
        }

        // ---- Cross-warp reduction through SMEM: red[w][b*64 + jj] ----
        {
            float* rw = smem + OFF_RED + w * 512;
            #pragma unroll
            for (int b = 0; b < 8; ++b)
                *(float2*)(rw + b * 64 + jj0) = make_float2(acc[b][0], acc[b][1]);
        }
        __syncthreads();

        float u = bi;
        #pragma unroll
        for (int ww = 0; ww < 16; ++ww)
            u += smem[OFF_RED + ww * 512 + tid];

        // ---- Oscillator update (thread owns (ob, ojj)) ----
        float v = tanhf(u);
        hz += RON_DT * (v - g * hy - e * hz);
        hy += RON_DT * hz;

        // states[b][t][j] = hy  (warp writes 128B coalesced: jj contiguous)
        out_states[(size_t)(b0 + ob) * Tx * Hx + (size_t)t * Hx + jbase + ojj] = hy;

        // ---- Push new hy to every CTA's next-phase mirror (incl. self) ----
        {
            uint32_t off = ((uint32_t)(jbase + ojj) * 8u + (uint32_t)ob) * 4u;
            #pragma unroll
            for (int q = 0; q < CLUSTER_SZ; ++q) {
                uint32_t a = (ph ? remA[q] : remB[q]) + off;  // write phase ph^1
                asm volatile("st.shared::cluster.f32 [%0], %1;" :: "r"(a), "f"(hy) : "memory");
            }
        }

        // One cluster barrier per step: orders DSMEM pushes (release->acquire),
        // xs double-buffer swap, and red reuse. Also acts as CTA-wide sync.
        cluster_barrier();
    }

    if (write_hy)
        out_hy[(size_t)(b0 + ob) * Hx + jbase + ojj] = hy;
}

extern "C" void kernel_launch(void* const* d_in, const int* in_sizes, int n_in,
                              void* d_out, int out_size) {
    const float* x     = (const float*)d_in[0];
    const float* x2h   = (const float*)d_in[1];
    const float* h2h   = (const float*)d_in[2];
    const float* bias  = (const float*)d_in[3];
    const float* gamma = (const float*)d_in[4];
    const float* eps   = (const float*)d_in[5];

    float* out_states = (float*)d_out;
    const size_t states_elems = (size_t)Bx * Tx * Hx;
    // Second output (final hy) concatenated after states, if the harness
    // allocated room for it.
    int write_hy = (out_size >= (int)(states_elems + (size_t)Bx * Hx)) ? 1 : 0;
    float* out_hy = out_states + states_elems;

    cudaFuncSetAttribute(ron_cluster_kernel,
                         cudaFuncAttributeMaxDynamicSharedMemorySize, (int)SMEM_BYTES);

    ron_cluster_kernel<<<dim3(Bx), dim3(NTHREADS), SMEM_BYTES>>>(
        x, x2h, h2h, bias, gamma, eps, out_states, out_hy, write_hy);
}

// round 5
// speedup vs baseline: 2.0786x; 2.0786x over previous
#include <cuda_runtime.h>
#include <cstdint>
#include <cstddef>

// Problem constants (fixed shapes for this bench)
#define RON_DT 0.042f
static constexpr int Bx = 128;   // batch
static constexpr int Tx = 1024;  // timesteps
static constexpr int Ix = 64;    // input dim
static constexpr int Hx = 512;   // hidden dim
static constexpr int NTHREADS = 512;

// Cluster partitioning: 16 clusters x 8 CTAs. Each cluster owns 8 batches,
// each CTA owns 64 j-columns of h2h (resident in SMEM for the whole run).
static constexpr int CLUSTER_SZ = 8;
static constexpr int JPC = 64;   // j columns per CTA
static constexpr int BPC = 8;    // batches per cluster

// SMEM layout (float offsets)
static constexpr int OFF_H2H = 0;                 // [512][64]  h2h column slice
static constexpr int OFF_X2H = 32768;             // [64][64]   x2h column slice
static constexpr int OFF_HY0 = 36864;             // [512][8]   hy mirror, phase 0 (k-major, b fastest)
static constexpr int OFF_HY1 = 40960;             // [512][8]   hy mirror, phase 1
static constexpr int OFF_XS0 = 45056;             // [64][8]    x staging, phase 0
static constexpr int OFF_XS1 = 45568;             // [64][8]    x staging, phase 1
static constexpr int OFF_RED = 46080;             // [16][512]  cross-warp reduction
static constexpr int SMEM_FLOATS = OFF_RED + 16 * 512;   // 54272 floats
static constexpr size_t SMEM_BYTES = (size_t)SMEM_FLOATS * 4;  // 217088 B

__device__ __forceinline__ uint32_t smem_u32(const void* p) {
    return (uint32_t)__cvta_generic_to_shared(p);
}

// 16 FMAs: 2 j-columns (w2) x 8 batches (ha: b0..3, hb: b4..7)
__device__ __forceinline__ void acc16(float (&acc)[8][2], float2 w2, float4 ha, float4 hb) {
    acc[0][0] = fmaf(ha.x, w2.x, acc[0][0]); acc[0][1] = fmaf(ha.x, w2.y, acc[0][1]);
    acc[1][0] = fmaf(ha.y, w2.x, acc[1][0]); acc[1][1] = fmaf(ha.y, w2.y, acc[1][1]);
    acc[2][0] = fmaf(ha.z, w2.x, acc[2][0]); acc[2][1] = fmaf(ha.z, w2.y, acc[2][1]);
    acc[3][0] = fmaf(ha.w, w2.x, acc[3][0]); acc[3][1] = fmaf(ha.w, w2.y, acc[3][1]);
    acc[4][0] = fmaf(hb.x, w2.x, acc[4][0]); acc[4][1] = fmaf(hb.x, w2.y, acc[4][1]);
    acc[5][0] = fmaf(hb.y, w2.x, acc[5][0]); acc[5][1] = fmaf(hb.y, w2.y, acc[5][1]);
    acc[6][0] = fmaf(hb.z, w2.x, acc[6][0]); acc[6][1] = fmaf(hb.z, w2.y, acc[6][1]);
    acc[7][0] = fmaf(hb.w, w2.x, acc[7][0]); acc[7][1] = fmaf(hb.w, w2.y, acc[7][1]);
}

extern __shared__ float smem[];

__global__ void __cluster_dims__(CLUSTER_SZ, 1, 1) __launch_bounds__(NTHREADS, 1)
ron_cluster_kernel(const float* __restrict__ x,
                   const float* __restrict__ x2h,
                   const float* __restrict__ h2h,
                   const float* __restrict__ bias,
                   const float* __restrict__ gamma,
                   const float* __restrict__ eps,
                   float* __restrict__ out_states,
                   float* __restrict__ out_hy,
                   int write_hy)
{
    const int tid  = threadIdx.x;
    const int w    = tid >> 5;     // warp 0..15 -> k-slice
    const int lane = tid & 31;

    uint32_t rank_u;
    asm("mov.u32 %0, %%cluster_ctarank;" : "=r"(rank_u));
    const int r     = (int)rank_u;            // j-slice owner within cluster
    const int cl    = blockIdx.x >> 3;        // cluster id
    const int b0    = cl * BPC;               // first global batch of this cluster
    const int jbase = r * JPC;                // first global j of this CTA

    // ---- Prologue: load weight slices into SMEM (once for all 1024 steps) ----
    #pragma unroll 4
    for (int it = 0; it < (Hx * JPC) / NTHREADS; ++it) {
        int idx = it * NTHREADS + tid;
        int k = idx >> 6, jj = idx & 63;
        smem[OFF_H2H + idx] = h2h[(size_t)k * Hx + jbase + jj];
    }
    #pragma unroll
    for (int it = 0; it < (Ix * JPC) / NTHREADS; ++it) {
        int idx = it * NTHREADS + tid;
        int i = idx >> 6, jj = idx & 63;
        smem[OFF_X2H + idx] = x2h[(size_t)i * Hx + jbase + jj];
    }
    // zero hy mirror phase 0 (initial hidden state)
    #pragma unroll
    for (int it = 0; it < (Hx * BPC) / NTHREADS; ++it)
        smem[OFF_HY0 + it * NTHREADS + tid] = 0.0f;

    // stage x for t=0 into xs phase 0: layout xs[i][b]
    {
        int bb = tid >> 6, i = tid & 63;
        smem[OFF_XS0 + i * 8 + bb] = x[(size_t)(b0 + bb) * Tx * Ix + i];
    }

    // Owner mapping for the update phase: thread tid owns (batch ob, column ojj)
    const int ob  = tid >> 6;
    const int ojj = tid & 63;
    const float g  = gamma[jbase + ojj];
    const float e  = eps[jbase + ojj];
    const float bi = bias[jbase + ojj];
    float hy = 0.0f, hz = 0.0f;

    // Push assignment: warps 0..13 copy the CTA's 512-float slab to the 7 peers
    // (2 warps per peer, 256 floats each, 8 coalesced 32-float warp-stores).
    const int push_peer = (r + 1 + (w >> 1)) & 7;            // peers r+1..r+7
    const int push_off  = jbase * 8 + (w & 1) * 256 + lane;  // float offset of first element

    // Remote DSMEM addresses (per phase) of this warp's first slab element in its peer.
    uint32_t pushA = 0, pushB = 0;
    {
        uint32_t locA = smem_u32(&smem[OFF_HY0 + push_off]);
        uint32_t locB = smem_u32(&smem[OFF_HY1 + push_off]);
        asm("mapa.shared::cluster.u32 %0, %1, %2;" : "=r"(pushA) : "r"(locA), "r"(push_peer));
        asm("mapa.shared::cluster.u32 %0, %1, %2;" : "=r"(pushB) : "r"(locB), "r"(push_peer));
    }

    asm volatile("barrier.cluster.arrive.aligned;" ::: "memory");
    asm volatile("barrier.cluster.wait.aligned;"   ::: "memory");

    const int k0 = w * 32;   // this warp's k slice (recurrent matvec)
    const int i0 = w * 4;    // this warp's i slice (input projection)
    const int jj0 = lane * 2;

    // x prefetch indices (plain LDG into register, STS at end of step)
    const int pf_b = tid >> 6, pf_i = tid & 63;
    const float* xsrc_base = x + (size_t)(b0 + pf_b) * Tx * Ix + pf_i;

    for (int t = 0; t < Tx; ++t) {
        const int ph = t & 1;
        const float* hyp  = smem + (ph ? OFF_HY1 : OFF_HY0);  // read mirror
        float*       wmir = smem + (ph ? OFF_HY0 : OFF_HY1);  // write mirror (next phase)
        const float* xr   = smem + (ph ? OFF_XS1 : OFF_XS0);
        float*       xw   = smem + (ph ? OFF_XS0 : OFF_XS1);

        // Issue next timestep's x load early; STS happens at end of step.
        float xnext = 0.0f;
        if (t + 1 < Tx)
            xnext = __ldg(xsrc_base + (size_t)(t + 1) * Ix);

        // ---- Partial matvec: this warp's k-slice, 2 j's x 8 batches per lane ----
        float acc[8][2];
        #pragma unroll
        for (int b = 0; b < 8; ++b) { acc[b][0] = 0.0f; acc[b][1] = 0.0f; }

        #pragma unroll 8
        for (int kk = 0; kk < 32; ++kk) {
            int k = k0 + kk;
            float2 w2 = *(const float2*)(smem + OFF_H2H + k * JPC + jj0);
            float4 ha = *(const float4*)(hyp + k * 8);
            float4 hb = *(const float4*)(hyp + k * 8 + 4);
            acc16(acc, w2, ha, hb);
        }
        #pragma unroll
        for (int ii = 0; ii < 4; ++ii) {
            int i = i0 + ii;
            float2 w2 = *(const float2*)(smem + OFF_X2H + i * JPC + jj0);
            float4 xa = *(const float4*)(xr + i * 8);
            float4 xb = *(const float4*)(xr + i * 8 + 4);
            acc16(acc, w2, xa, xb);
        }

        // ---- Cross-warp reduction through SMEM: red[w][b*64 + jj] ----
        {
            float* rw = smem + OFF_RED + w * 512;
            #pragma unroll
            for (int b = 0; b < 8; ++b)
                *(float2*)(rw + b * 64 + jj0) = make_float2(acc[b][0], acc[b][1]);
        }
        __syncthreads();

        float u = bi;
        #pragma unroll
        for (int ww = 0; ww < 16; ++ww)
            u += smem[OFF_RED + ww * 512 + tid];

        // ---- Oscillator update (thread owns (ob, ojj)) ----
        float v;
        asm("tanh.approx.f32 %0, %1;" : "=f"(v) : "f"(u));
        hz += RON_DT * (v - g * hy - e * hz);
        hy += RON_DT * hz;

        // Store hy once into OWN next-phase mirror slab (contiguous 2KB region)
        wmir[(jbase + ojj) * 8 + ob] = hy;
        __syncthreads();   // slab complete; also: all reads of hyp/red done

        // ---- Bulk-push own slab to the 7 peers: coalesced scalar remote stores ----
        if (w < 14) {
            const float* src = wmir + push_off;
            const uint32_t dstb = ph ? pushA : pushB;   // next-phase mirror in peer
            #pragma unroll
            for (int it = 0; it < 8; ++it) {
                float val = src[it * 32];
                asm volatile("st.shared::cluster.f32 [%0], %1;"
                             :: "r"(dstb + (uint32_t)(it * 32 * 4)), "f"(val) : "memory");
            }
        }

        // Stage prefetched x for next step (xw is not read by anyone this step)
        if (t + 1 < Tx)
            xw[pf_i * 8 + pf_b] = xnext;

        // Release pushes; overlap the out_states STG with peers' arrival
        asm volatile("barrier.cluster.arrive.aligned;" ::: "memory");

        out_states[(size_t)(b0 + ob) * Tx * Hx + (size_t)t * Hx + jbase + ojj] = hy;

        asm volatile("barrier.cluster.wait.aligned;" ::: "memory");
    }

    if (write_hy)
        out_hy[(size_t)(b0 + ob) * Hx + jbase + ojj] = hy;
}

extern "C" void kernel_launch(void* const* d_in, const int* in_sizes, int n_in,
                              void* d_out, int out_size) {
    const float* x     = (const float*)d_in[0];
    const float* x2h   = (const float*)d_in[1];
    const float* h2h   = (const float*)d_in[2];
    const float* bias  = (const float*)d_in[3];
    const float* gamma = (const float*)d_in[4];
    const float* eps   = (const float*)d_in[5];

    float* out_states = (float*)d_out;
    const size_t states_elems = (size_t)Bx * Tx * Hx;
    int write_hy = (out_size >= (int)(states_elems + (size_t)Bx * Hx)) ? 1 : 0;
    float* out_hy = out_states + states_elems;

    cudaFuncSetAttribute(ron_cluster_kernel,
                         cudaFuncAttributeMaxDynamicSharedMemorySize, (int)SMEM_BYTES);

    ron_cluster_kernel<<<dim3(Bx), dim3(NTHREADS), SMEM_BYTES>>>(
        x, x2h, h2h, bias, gamma, eps, out_states, out_hy, write_hy);
}

// round 6
// speedup vs baseline: 2.7285x; 1.3126x over previous
#include <cuda_runtime.h>
#include <cstdint>
#include <cstddef>

// Problem constants (fixed shapes for this bench)
#define RON_DT 0.042f
static constexpr int Bx = 128;   // batch
static constexpr int Tx = 1024;  // timesteps
static constexpr int Ix = 64;    // input dim
static constexpr int Hx = 512;   // hidden dim
static constexpr int NTHREADS = 512;

// Cluster partitioning: 16 clusters x 8 CTAs. Each cluster owns 8 batches,
// each CTA owns 64 j-columns. h2h weights live in REGISTERS (64/thread).
static constexpr int CLUSTER_SZ = 8;
static constexpr int JPC = 64;   // j columns per CTA
static constexpr int BPC = 8;    // batches per cluster

// SMEM layout (float offsets) — h2h no longer in SMEM
static constexpr int OFF_X2H = 0;          // [64][64]   x2h column slice
static constexpr int OFF_HY0 = 4096;       // [512][8]   hy mirror, phase 0 (k-major, b fastest)
static constexpr int OFF_HY1 = 8192;       // [512][8]   hy mirror, phase 1
static constexpr int OFF_XS0 = 12288;      // [64][8]    x staging, phase 0
static constexpr int OFF_XS1 = 12800;      // [64][8]    x staging, phase 1
static constexpr int OFF_RED = 13312;      // [16][512]  cross-warp reduction
static constexpr int SMEM_FLOATS = OFF_RED + 16 * 512;   // 21504 floats
static constexpr size_t SMEM_BYTES = (size_t)SMEM_FLOATS * 4;  // 86016 B

__device__ __forceinline__ uint32_t smem_u32(const void* p) {
    return (uint32_t)__cvta_generic_to_shared(p);
}

__device__ __forceinline__ uint64_t pack2(float lo, float hi) {
    uint64_t d;
    asm("mov.b64 %0, {%1, %2};" : "=l"(d) : "f"(lo), "f"(hi));
    return d;
}

__device__ __forceinline__ uint64_t fma2(uint64_t a, uint64_t b, uint64_t c) {
    uint64_t d;
    asm("fma.rn.f32x2 %0, %1, %2, %3;" : "=l"(d) : "l"(a), "l"(b), "l"(c));
    return d;
}

// 8 packed FMA2 = 16 scalar FMAs: batch-pairs h01..h67 x packed-splat weights wxx/wyy
__device__ __forceinline__ void accp16(uint64_t (&acc)[4][2], uint64_t wxx, uint64_t wyy,
                                       uint64_t h01, uint64_t h23, uint64_t h45, uint64_t h67) {
    acc[0][0] = fma2(h01, wxx, acc[0][0]); acc[0][1] = fma2(h01, wyy, acc[0][1]);
    acc[1][0] = fma2(h23, wxx, acc[1][0]); acc[1][1] = fma2(h23, wyy, acc[1][1]);
    acc[2][0] = fma2(h45, wxx, acc[2][0]); acc[2][1] = fma2(h45, wyy, acc[2][1]);
    acc[3][0] = fma2(h67, wxx, acc[3][0]); acc[3][1] = fma2(h67, wyy, acc[3][1]);
}

extern __shared__ float smem[];

__global__ void __cluster_dims__(CLUSTER_SZ, 1, 1) __launch_bounds__(NTHREADS, 1)
ron_cluster_kernel(const float* __restrict__ x,
                   const float* __restrict__ x2h,
                   const float* __restrict__ h2h,
                   const float* __restrict__ bias,
                   const float* __restrict__ gamma,
                   const float* __restrict__ eps,
                   float* __restrict__ out_states,
                   float* __restrict__ out_hy,
                   int write_hy)
{
    const int tid  = threadIdx.x;
    const int w    = tid >> 5;     // warp 0..15 -> k-slice
    const int lane = tid & 31;

    uint32_t rank_u;
    asm("mov.u32 %0, %%cluster_ctarank;" : "=r"(rank_u));
    const int r     = (int)rank_u;            // j-slice owner within cluster
    const int cl    = blockIdx.x >> 3;        // cluster id
    const int b0    = cl * BPC;               // first global batch of this cluster
    const int jbase = r * JPC;                // first global j of this CTA

    const int k0  = w * 32;    // this warp's k slice (recurrent matvec)
    const int i0  = w * 4;     // this warp's i slice (input projection)
    const int jj0 = lane * 2;  // this lane's j pair

    // ---- Prologue ----
    // h2h weights into REGISTERS: thread holds w[kk] = (h2h[k0+kk][jbase+jj0], ...+1)
    float2 wreg[32];
    {
        const float2* src = reinterpret_cast<const float2*>(h2h + (size_t)k0 * Hx + jbase + jj0);
        #pragma unroll
        for (int kk = 0; kk < 32; ++kk)
            wreg[kk] = __ldg(src + (size_t)kk * (Hx / 2));
    }
    // x2h slice into SMEM: [64][64]
    #pragma unroll
    for (int it = 0; it < (Ix * JPC) / NTHREADS; ++it) {
        int idx = it * NTHREADS + tid;
        int i = idx >> 6, jj = idx & 63;
        smem[OFF_X2H + idx] = x2h[(size_t)i * Hx + jbase + jj];
    }
    // zero hy mirror phase 0 (initial hidden state)
    #pragma unroll
    for (int it = 0; it < (Hx * BPC) / NTHREADS; ++it)
        smem[OFF_HY0 + it * NTHREADS + tid] = 0.0f;

    // stage x for t=0 into xs phase 0: layout xs[i][b]
    {
        int bb = tid >> 6, i = tid & 63;
        smem[OFF_XS0 + i * 8 + bb] = x[(size_t)(b0 + bb) * Tx * Ix + i];
    }

    // Owner mapping for the update phase: thread tid owns (batch ob, column ojj)
    const int ob  = tid >> 6;
    const int ojj = tid & 63;
    const float g  = gamma[jbase + ojj];
    const float e  = eps[jbase + ojj];
    const float bi = bias[jbase + ojj];
    float hy = 0.0f, hz = 0.0f;

    // Push assignment: warps 0..13 copy the CTA's 512-float slab to the 7 peers
    const int push_peer = (r + 1 + (w >> 1)) & 7;            // peers r+1..r+7
    const int push_off  = jbase * 8 + (w & 1) * 256 + lane;  // float offset of first element

    uint32_t pushA = 0, pushB = 0;
    {
        uint32_t locA = smem_u32(&smem[OFF_HY0 + push_off]);
        uint32_t locB = smem_u32(&smem[OFF_HY1 + push_off]);
        asm("mapa.shared::cluster.u32 %0, %1, %2;" : "=r"(pushA) : "r"(locA), "r"(push_peer));
        asm("mapa.shared::cluster.u32 %0, %1, %2;" : "=r"(pushB) : "r"(locB), "r"(push_peer));
    }

    asm volatile("barrier.cluster.arrive.aligned;" ::: "memory");
    asm volatile("barrier.cluster.wait.aligned;"   ::: "memory");

    // Shared-space base addresses for asm LDS
    const uint32_t hy0_base = smem_u32(&smem[OFF_HY0]) + (uint32_t)k0 * 32u;
    const uint32_t hy1_base = smem_u32(&smem[OFF_HY1]) + (uint32_t)k0 * 32u;
    const uint32_t xs0_base = smem_u32(&smem[OFF_XS0]) + (uint32_t)i0 * 32u;
    const uint32_t xs1_base = smem_u32(&smem[OFF_XS1]) + (uint32_t)i0 * 32u;

    // x prefetch indices (plain LDG into register, STS at end of step)
    const int pf_b = tid >> 6, pf_i = tid & 63;
    const float* xsrc_base = x + (size_t)(b0 + pf_b) * Tx * Ix + pf_i;

    for (int t = 0; t < Tx; ++t) {
        const int ph = t & 1;
        const uint32_t hyp_b = ph ? hy1_base : hy0_base;      // read mirror (this warp's k slice)
        const uint32_t xr_b  = ph ? xs1_base : xs0_base;      // x staging (this warp's i slice)
        float* wmir = smem + (ph ? OFF_HY0 : OFF_HY1);        // write mirror (next phase)
        float* xw   = smem + (ph ? OFF_XS0 : OFF_XS1);

        // Issue next timestep's x load early; STS happens at end of step.
        float xnext = 0.0f;
        if (t + 1 < Tx)
            xnext = __ldg(xsrc_base + (size_t)(t + 1) * Ix);

        // ---- Partial matvec: packed f32x2, weights from registers ----
        uint64_t acc[4][2];
        #pragma unroll
        for (int p = 0; p < 4; ++p) { acc[p][0] = 0ull; acc[p][1] = 0ull; }

        #pragma unroll
        for (int kk = 0; kk < 32; ++kk) {
            uint64_t h01, h23, h45, h67;
            uint32_t a = hyp_b + (uint32_t)kk * 32u;
            asm("ld.shared.v2.u64 {%0, %1}, [%2];"      : "=l"(h01), "=l"(h23) : "r"(a));
            asm("ld.shared.v2.u64 {%0, %1}, [%2 + 16];" : "=l"(h45), "=l"(h67) : "r"(a));
            uint64_t wxx = pack2(wreg[kk].x, wreg[kk].x);
            uint64_t wyy = pack2(wreg[kk].y, wreg[kk].y);
            accp16(acc, wxx, wyy, h01, h23, h45, h67);
        }
        // Input projection slice (i-range of this warp), x2h weights from SMEM
        #pragma unroll
        for (int ii = 0; ii < 4; ++ii) {
            float2 w2 = *(const float2*)(smem + OFF_X2H + (i0 + ii) * JPC + jj0);
            uint64_t h01, h23, h45, h67;
            uint32_t a = xr_b + (uint32_t)ii * 32u;
            asm("ld.shared.v2.u64 {%0, %1}, [%2];"      : "=l"(h01), "=l"(h23) : "r"(a));
            asm("ld.shared.v2.u64 {%0, %1}, [%2 + 16];" : "=l"(h45), "=l"(h67) : "r"(a));
            uint64_t wxx = pack2(w2.x, w2.x);
            uint64_t wyy = pack2(w2.y, w2.y);
            accp16(acc, wxx, wyy, h01, h23, h45, h67);
        }

        // ---- Cross-warp reduction through SMEM: red[w][b*64 + jj] ----
        {
            float* rw = smem + OFF_RED + w * 512;
            #pragma unroll
            for (int p = 0; p < 4; ++p) {
                float l0, h0, l1, h1;
                asm("mov.b64 {%0, %1}, %2;" : "=f"(l0), "=f"(h0) : "l"(acc[p][0]));
                asm("mov.b64 {%0, %1}, %2;" : "=f"(l1), "=f"(h1) : "l"(acc[p][1]));
                *(float2*)(rw + (2 * p)     * 64 + jj0) = make_float2(l0, l1);
                *(float2*)(rw + (2 * p + 1) * 64 + jj0) = make_float2(h0, h1);
            }
        }
        __syncthreads();

        float u = bi;
        #pragma unroll
        for (int ww = 0; ww < 16; ++ww)
            u += smem[OFF_RED + ww * 512 + tid];

        // ---- Oscillator update (thread owns (ob, ojj)) ----
        float v;
        asm("tanh.approx.f32 %0, %1;" : "=f"(v) : "f"(u));
        hz += RON_DT * (v - g * hy - e * hz);
        hy += RON_DT * hz;

        // Store hy once into OWN next-phase mirror slab (contiguous 2KB region)
        wmir[(jbase + ojj) * 8 + ob] = hy;
        __syncthreads();   // slab complete; also: all reads of hyp/red done

        // ---- Bulk-push own slab to the 7 peers: coalesced scalar remote stores ----
        if (w < 14) {
            const float* src = wmir + push_off;
            const uint32_t dstb = ph ? pushA : pushB;   // next-phase mirror in peer
            #pragma unroll
            for (int it = 0; it < 8; ++it) {
                float val = src[it * 32];
                asm volatile("st.shared::cluster.f32 [%0], %1;"
                             :: "r"(dstb + (uint32_t)(it * 32 * 4)), "f"(val) : "memory");
            }
        }

        // Stage prefetched x for next step (xw is not read by anyone this step)
        if (t + 1 < Tx)
            xw[pf_i * 8 + pf_b] = xnext;

        // Release pushes; overlap the out_states STG with peers' arrival
        asm volatile("barrier.cluster.arrive.aligned;" ::: "memory");

        out_states[(size_t)(b0 + ob) * Tx * Hx + (size_t)t * Hx + jbase + ojj] = hy;

        asm volatile("barrier.cluster.wait.aligned;" ::: "memory");
    }

    if (write_hy)
        out_hy[(size_t)(b0 + ob) * Hx + jbase + ojj] = hy;
}

extern "C" void kernel_launch(void* const* d_in, const int* in_sizes, int n_in,
                              void* d_out, int out_size) {
    const float* x     = (const float*)d_in[0];
    const float* x2h   = (const float*)d_in[1];
    const float* h2h   = (const float*)d_in[2];
    const float* bias  = (const float*)d_in[3];
    const float* gamma = (const float*)d_in[4];
    const float* eps   = (const float*)d_in[5];

    float* out_states = (float*)d_out;
    const size_t states_elems = (size_t)Bx * Tx * Hx;
    int write_hy = (out_size >= (int)(states_elems + (size_t)Bx * Hx)) ? 1 : 0;
    float* out_hy = out_states + states_elems;

    cudaFuncSetAttribute(ron_cluster_kernel,
                         cudaFuncAttributeMaxDynamicSharedMemorySize, (int)SMEM_BYTES);

    ron_cluster_kernel<<<dim3(Bx), dim3(NTHREADS), SMEM_BYTES>>>(
        x, x2h, h2h, bias, gamma, eps, out_states, out_hy, write_hy);
}